// round 1
// baseline (speedup 1.0000x reference)
#include <cuda_runtime.h>
#include <cstdint>
#include <cstdio>

// ---------------------------------------------------------------------------
// KANClassifier: x[4096,1024] -> tanh basis feats[4096,16384] -> GEMM1(+bb,
// sigmoid) -> phi[4096,4096] -> GEMM2(+bh) -> logits[4096,1000]
// ---------------------------------------------------------------------------

#define BATCH   4096
#define IN_DIM  1024
#define NBASIS  16
#define KDIM    16384     // IN_DIM * NBASIS
#define HIDDEN  4096
#define CLASSES 1000
#define NPAD    1024      // padded classes for tiling

// Scratch (allowed: __device__ globals, no runtime allocation)
__device__ float g_F[(size_t)BATCH * KDIM];     // feature matrix, fp32
__device__ float g_PHI[(size_t)BATCH * HIDDEN]; // sigmoid activations, fp32

// ---------------------------------------------------------------------------
// Kernel 1: tanh basis expansion. One thread per (b, d); 16 basis each.
// ---------------------------------------------------------------------------
__global__ void feats_kernel(const float* __restrict__ x,
                             const float* __restrict__ centers,
                             const float* __restrict__ scales,
                             float* __restrict__ F) {
    int idx = blockIdx.x * blockDim.x + threadIdx.x; // b*IN_DIM + d
    if (idx >= BATCH * IN_DIM) return;
    int d = idx & (IN_DIM - 1);
    float xv = __ldg(x + idx);
    const float4* c4 = reinterpret_cast<const float4*>(centers) + d * 4;
    const float4* s4 = reinterpret_cast<const float4*>(scales) + d * 4;
    float4* dst = reinterpret_cast<float4*>(F) + (size_t)idx * 4;
#pragma unroll
    for (int i = 0; i < 4; i++) {
        float4 c = __ldg(c4 + i);
        float4 s = __ldg(s4 + i);
        float4 o;
        o.x = tanhf((xv - c.x) * s.x);
        o.y = tanhf((xv - c.y) * s.y);
        o.z = tanhf((xv - c.z) * s.z);
        o.w = tanhf((xv - c.w) * s.w);
        dst[i] = o;
    }
}

// ---------------------------------------------------------------------------
// Kernel 2: tf32 mma.sync GEMM.  C[M,N] = A[M,K] @ B[K,N] + bias (opt sigmoid)
// A row-major lda=K, B row-major ldb=Nreal, C row-major ldc=Nreal.
// Block tile 128x128x32, 8 warps (2 M x 4 N), warp tile 64x32, m16n8k8 tf32.
// cp.async double-buffered. NGUARD handles Nreal not multiple of tile.
// ---------------------------------------------------------------------------
#define BM 128
#define BN 128
#define BK 32
#define AS_STRIDE 36      // BK + 4 pad  -> conflict-free A frag loads
#define BS_STRIDE 136     // BN + 8 pad  -> conflict-free B frag loads
#define AS_SIZE (BM * AS_STRIDE)
#define BS_SIZE (BK * BS_STRIDE)
#define SMEM_BYTES (2 * (AS_SIZE + BS_SIZE) * 4)

__device__ __forceinline__ uint32_t f2tf32(float f) {
    uint32_t u;
    asm("cvt.rna.tf32.f32 %0, %1;" : "=r"(u) : "f"(f));
    return u;
}

__device__ __forceinline__ void cp_async16(uint32_t saddr, const void* gptr, int src_bytes) {
    asm volatile("cp.async.cg.shared.global [%0], [%1], 16, %2;\n"
                 :: "r"(saddr), "l"(gptr), "r"(src_bytes));
}

template <bool SIGMOID, bool NGUARD>
__global__ void __launch_bounds__(256, 2)
gemm_tf32_kernel(const float* __restrict__ A,
                 const float* __restrict__ B,
                 const float* __restrict__ bias,
                 float* __restrict__ C,
                 int K, int Nreal) {
    extern __shared__ float smem[];
    float* As = smem;                 // [2][BM][AS_STRIDE]
    float* Bs = smem + 2 * AS_SIZE;   // [2][BK][BS_STRIDE]

    const int tid  = threadIdx.x;
    const int lane = tid & 31;
    const int warp = tid >> 5;
    const int wm   = warp & 1;   // warp row (2 along M)
    const int wn   = warp >> 1;  // warp col (4 along N)

    const int bm0 = blockIdx.y * BM;
    const int bn0 = blockIdx.x * BN;

    // global->smem coords
    const int a_row  = tid >> 3;          // 0..31, +32 per pass (4 passes)
    const int a_col  = (tid & 7) * 4;     // float4 within BK
    const int b_rowt = tid >> 5;          // 0..7, +8 per pass (4 passes)
    const int b_colt = (tid & 31) * 4;    // float4 within BN

    float acc[4][4][4];
#pragma unroll
    for (int i = 0; i < 4; i++)
#pragma unroll
        for (int j = 0; j < 4; j++)
#pragma unroll
            for (int k = 0; k < 4; k++) acc[i][j][k] = 0.f;

    const int KT = K / BK;

    auto load_stage = [&](int kt, int stage) {
        float* as = As + stage * AS_SIZE;
        float* bs = Bs + stage * BS_SIZE;
        const float* Ag = A + (size_t)(bm0 + a_row) * K + kt * BK + a_col;
#pragma unroll
        for (int i = 0; i < 4; i++) {
            uint32_t sa = (uint32_t)__cvta_generic_to_shared(
                as + (a_row + i * 32) * AS_STRIDE + a_col);
            cp_async16(sa, Ag + (size_t)i * 32 * K, 16);
        }
#pragma unroll
        for (int i = 0; i < 4; i++) {
            int row = b_rowt + i * 8;
            int col = bn0 + b_colt;
            const float* gp = B + (size_t)(kt * BK + row) * Nreal + col;
            int sz = 16;
            if (NGUARD && col >= Nreal) { gp = B; sz = 0; }
            uint32_t sb = (uint32_t)__cvta_generic_to_shared(
                bs + row * BS_STRIDE + b_colt);
            cp_async16(sb, gp, sz);
        }
        asm volatile("cp.async.commit_group;\n");
    };

    load_stage(0, 0);

    for (int kt = 0; kt < KT; kt++) {
        int stage = kt & 1;
        if (kt + 1 < KT) {
            load_stage(kt + 1, stage ^ 1);
            asm volatile("cp.async.wait_group 1;\n");
        } else {
            asm volatile("cp.async.wait_group 0;\n");
        }
        __syncthreads();

        const float* as = As + stage * AS_SIZE;
        const float* bs = Bs + stage * BS_SIZE;

#pragma unroll
        for (int ks = 0; ks < 4; ks++) {
            const int kk = ks * 8 + (lane & 3);
            uint32_t af[4][4];
            uint32_t bf[4][2];
            const int r0base = wm * 64 + (lane >> 2);
#pragma unroll
            for (int mf = 0; mf < 4; mf++) {
                int r0 = r0base + mf * 16;
                af[mf][0] = f2tf32(as[r0 * AS_STRIDE + kk]);
                af[mf][1] = f2tf32(as[(r0 + 8) * AS_STRIDE + kk]);
                af[mf][2] = f2tf32(as[r0 * AS_STRIDE + kk + 4]);
                af[mf][3] = f2tf32(as[(r0 + 8) * AS_STRIDE + kk + 4]);
            }
            const int cb0 = wn * 32 + (lane >> 2);
#pragma unroll
            for (int nf = 0; nf < 4; nf++) {
                int cb = cb0 + nf * 8;
                bf[nf][0] = f2tf32(bs[kk * BS_STRIDE + cb]);
                bf[nf][1] = f2tf32(bs[(kk + 4) * BS_STRIDE + cb]);
            }
#pragma unroll
            for (int mf = 0; mf < 4; mf++)
#pragma unroll
                for (int nf = 0; nf < 4; nf++)
                    asm volatile(
                        "mma.sync.aligned.m16n8k8.row.col.f32.tf32.tf32.f32 "
                        "{%0,%1,%2,%3}, {%4,%5,%6,%7}, {%8,%9}, {%0,%1,%2,%3};\n"
                        : "+f"(acc[mf][nf][0]), "+f"(acc[mf][nf][1]),
                          "+f"(acc[mf][nf][2]), "+f"(acc[mf][nf][3])
                        : "r"(af[mf][0]), "r"(af[mf][1]),
                          "r"(af[mf][2]), "r"(af[mf][3]),
                          "r"(bf[nf][0]), "r"(bf[nf][1]));
        }
        __syncthreads();
    }

    // Epilogue: bias (+ sigmoid) + store
#pragma unroll
    for (int mf = 0; mf < 4; mf++) {
        int r0 = bm0 + wm * 64 + mf * 16 + (lane >> 2);
#pragma unroll
        for (int nf = 0; nf < 4; nf++) {
            int c0 = bn0 + wn * 32 + nf * 8 + (lane & 3) * 2;
#pragma unroll
            for (int half = 0; half < 2; half++) {
                int r = r0 + half * 8;
#pragma unroll
                for (int e = 0; e < 2; e++) {
                    int c = c0 + e;
                    if (NGUARD && c >= Nreal) continue;
                    float v = acc[mf][nf][half * 2 + e] + __ldg(bias + c);
                    if (SIGMOID) v = 1.f / (1.f + __expf(-v));
                    C[(size_t)r * Nreal + c] = v;
                }
            }
        }
    }
}

// ---------------------------------------------------------------------------
// Launch
// ---------------------------------------------------------------------------
extern "C" void kernel_launch(void* const* d_in, const int* in_sizes, int n_in,
                              void* d_out, int out_size) {
    const float* x       = (const float*)d_in[0];
    const float* centers = (const float*)d_in[1];
    const float* scales  = (const float*)d_in[2];
    const float* Wb      = (const float*)d_in[3];
    const float* bb      = (const float*)d_in[4];
    const float* Wh      = (const float*)d_in[5];
    const float* bh      = (const float*)d_in[6];
    float* out = (float*)d_out;

    float* F = nullptr;
    float* PHI = nullptr;
    cudaGetSymbolAddress((void**)&F, g_F);
    cudaGetSymbolAddress((void**)&PHI, g_PHI);

    static_assert(SMEM_BYTES <= 100 * 1024, "smem");
    cudaFuncSetAttribute(gemm_tf32_kernel<true, false>,
                         cudaFuncAttributeMaxDynamicSharedMemorySize, SMEM_BYTES);
    cudaFuncSetAttribute(gemm_tf32_kernel<false, true>,
                         cudaFuncAttributeMaxDynamicSharedMemorySize, SMEM_BYTES);

    // 1) tanh basis expansion
    {
        int n = BATCH * IN_DIM;
        feats_kernel<<<(n + 255) / 256, 256>>>(x, centers, scales, F);
    }
    // 2) GEMM1: phi = sigmoid(F @ Wb + bb)   [4096,16384]x[16384,4096]
    {
        dim3 grid(HIDDEN / BN, BATCH / BM);
        gemm_tf32_kernel<true, false><<<grid, 256, SMEM_BYTES>>>(
            F, Wb, bb, PHI, KDIM, HIDDEN);
    }
    // 3) GEMM2: logits = phi @ Wh + bh       [4096,4096]x[4096,1000]
    {
        dim3 grid(NPAD / BN, BATCH / BM);
        gemm_tf32_kernel<false, true><<<grid, 256, SMEM_BYTES>>>(
            PHI, Wh, bh, out, HIDDEN, CLASSES);
    }
}

// round 3
// speedup vs baseline: 1.0444x; 1.0444x over previous
#include <cuda_runtime.h>
#include <cstdint>

// ---------------------------------------------------------------------------
// KANClassifier (sm_103 toolchain => no tcgen05; tuned mma.sync tf32 path)
//   feats (tanh basis, writes F pre-rounded tf32 in GEMM1-fragment-packed
//   layout) -> GEMM1 128x256 tiles, LDS.128 A frags, no in-loop cvt,
//   bias+sigmoid epilogue -> GEMM2 (round-1 style) -> logits
// ---------------------------------------------------------------------------

#define BATCH   4096
#define IN_DIM  1024
#define KDIM    16384
#define HIDDEN  4096
#define CLASSES 1000
#define NPAD    1024

__device__ __align__(1024) float g_F  [(size_t)BATCH * KDIM];   // packed A
__device__ __align__(1024) float g_PHI[(size_t)BATCH * HIDDEN]; // row-major

__device__ __forceinline__ uint32_t f2tf32(float f) {
    uint32_t u;
    asm("cvt.rna.tf32.f32 %0, %1;" : "=r"(u) : "f"(f));
    return u;
}
__device__ __forceinline__ float tf32r(float f) { return __uint_as_float(f2tf32(f)); }

__device__ __forceinline__ void cp_async16(uint32_t saddr, const void* gptr) {
    asm volatile("cp.async.cg.shared.global [%0], [%1], 16;\n" :: "r"(saddr), "l"(gptr));
}

// ---------------------------------------------------------------------------
// Kernel 1: tanh basis -> g_F in packed layout.
// Packed layout per (mt, kt) tile of [128 rows x 32 k]: 4096 floats.
//   idx(r,k): ks=k>>3, kl=k&7, klane=kl&3, khi=kl>>2; grp=r>>4, rlo=r&7,
//             rhi=(r>>3)&1;  idx = ks*1024 + grp*128 + rlo*16 + klane*4
//                                  + khi*2 + rhi
// One thread per 16B chunk (4 elems = rows {r,r+8} x k {k,k+4}).
// ---------------------------------------------------------------------------
__global__ void feats_packed_kernel(const float* __restrict__ x,
                                    const float* __restrict__ centers,
                                    const float* __restrict__ scales,
                                    float* __restrict__ F) {
    int g = blockIdx.x * blockDim.x + threadIdx.x;   // chunk id
    int w   = g & 1023;
    int kt  = (g >> 10) & 511;
    int mt  = g >> 19;
    int ks  = w >> 8;
    int grp = (w >> 5) & 7;
    int rlo = (w >> 2) & 7;
    int kl  = w & 3;
    int b0 = mt * 128 + grp * 16 + rlo;      // row (rhi=0); +8 for rhi=1
    int kg = kt * 32 + ks * 8 + kl;          // k (khi=0); +4 for khi=1
    int d  = kg >> 4;
    int j0 = kg & 15;                         // j0+4 stays in same d (<16)

    float xv0 = __ldg(x + (size_t)b0 * IN_DIM + d);
    float xv1 = __ldg(x + (size_t)(b0 + 8) * IN_DIM + d);
    float c0 = __ldg(centers + d * 16 + j0);
    float c1 = __ldg(centers + d * 16 + j0 + 4);
    float s0 = __ldg(scales  + d * 16 + j0);
    float s1 = __ldg(scales  + d * 16 + j0 + 4);

    float4 o;
    o.x = tf32r(tanhf((xv0 - c0) * s0));   // (r,   k)
    o.y = tf32r(tanhf((xv1 - c0) * s0));   // (r+8, k)
    o.z = tf32r(tanhf((xv0 - c1) * s1));   // (r,   k+4)
    o.w = tf32r(tanhf((xv1 - c1) * s1));   // (r+8, k+4)
    reinterpret_cast<float4*>(F)[g] = o;
}

// ---------------------------------------------------------------------------
// GEMM1: PHI = sigmoid(Fpacked @ Wb + bb)   [4096,16384]x[16384,4096]
// Block 128x256x32, 8 warps (2M x 4N), warp tile 64x64, 3-stage cp.async.
// ---------------------------------------------------------------------------
#define G1_BK       32
#define G1_STAGES   3
#define G1_A_FLTS   4096            // 16KB per stage (packed)
#define G1_B_STRIDE 264             // 256 + 8 pad floats
#define G1_B_FLTS   (32 * G1_B_STRIDE)
#define G1_SMEM     (G1_STAGES * (G1_A_FLTS + G1_B_FLTS) * 4)

__global__ void __launch_bounds__(256, 1)
gemm1_kernel(const float* __restrict__ Apk,   // g_F packed
             const float* __restrict__ B,     // Wb row-major [KDIM][HIDDEN]
             const float* __restrict__ bias,
             float* __restrict__ C) {         // PHI row-major
    extern __shared__ float sm[];
    float* As = sm;
    float* Bs = sm + G1_STAGES * G1_A_FLTS;

    const int tid  = threadIdx.x;
    const int lane = tid & 31;
    const int warp = tid >> 5;
    const int wm = warp & 1, wn = warp >> 1;
    const int lr = lane >> 2, lc = lane & 3;
    const int mt = blockIdx.y;
    const int n0 = blockIdx.x * 256;
    const int m0 = mt * 128;
    const int KT = KDIM / G1_BK;   // 512

    float acc[4][8][4];
#pragma unroll
    for (int i = 0; i < 4; i++)
#pragma unroll
        for (int j = 0; j < 8; j++)
#pragma unroll
            for (int k = 0; k < 4; k++) acc[i][j][k] = 0.f;

    auto load_stage = [&](int kt, int s) {
        const float* ag = Apk + ((size_t)mt * KT + kt) * G1_A_FLTS;
        float* as = As + s * G1_A_FLTS;
#pragma unroll
        for (int p = 0; p < 4; p++) {
            int ci = tid + p * 256;
            cp_async16((uint32_t)__cvta_generic_to_shared(as + ci * 4), ag + ci * 4);
        }
        const float* bg = B + (size_t)(kt * 32) * HIDDEN + n0;
        float* bs = Bs + s * G1_B_FLTS;
#pragma unroll
        for (int p = 0; p < 8; p++) {
            int ci = tid + p * 256;
            int row = ci >> 6, cc = ci & 63;
            cp_async16((uint32_t)__cvta_generic_to_shared(bs + row * G1_B_STRIDE + cc * 4),
                       bg + (size_t)row * HIDDEN + cc * 4);
        }
    };

    load_stage(0, 0);
    asm volatile("cp.async.commit_group;\n");
    load_stage(1, 1);
    asm volatile("cp.async.commit_group;\n");

    for (int kt = 0; kt < KT; kt++) {
        if (kt + 2 < KT) load_stage(kt + 2, (kt + 2) % G1_STAGES);
        asm volatile("cp.async.commit_group;\n");
        asm volatile("cp.async.wait_group 2;\n");
        __syncthreads();

        const int s = kt % G1_STAGES;
        const float* as = As + s * G1_A_FLTS;
        const float* bs = Bs + s * G1_B_FLTS;

#pragma unroll
        for (int ks = 0; ks < 4; ks++) {
            uint32_t af[4][4];
#pragma unroll
            for (int mf = 0; mf < 4; mf++) {
                float4 v = *reinterpret_cast<const float4*>(
                    as + ks * 1024 + (wm * 4 + mf) * 128 + lr * 16 + lc * 4);
                af[mf][0] = __float_as_uint(v.x);
                af[mf][1] = __float_as_uint(v.y);
                af[mf][2] = __float_as_uint(v.z);
                af[mf][3] = __float_as_uint(v.w);
            }
            uint32_t bf[8][2];
            const float* bp = bs + (ks * 8 + lc) * G1_B_STRIDE + wn * 64 + lr;
#pragma unroll
            for (int nf = 0; nf < 8; nf++) {
                bf[nf][0] = __float_as_uint(bp[nf * 8]);
                bf[nf][1] = __float_as_uint(bp[nf * 8 + 4 * G1_B_STRIDE]);
            }
#pragma unroll
            for (int mf = 0; mf < 4; mf++)
#pragma unroll
                for (int nf = 0; nf < 8; nf++)
                    asm volatile(
                        "mma.sync.aligned.m16n8k8.row.col.f32.tf32.tf32.f32 "
                        "{%0,%1,%2,%3}, {%4,%5,%6,%7}, {%8,%9}, {%0,%1,%2,%3};\n"
                        : "+f"(acc[mf][nf][0]), "+f"(acc[mf][nf][1]),
                          "+f"(acc[mf][nf][2]), "+f"(acc[mf][nf][3])
                        : "r"(af[mf][0]), "r"(af[mf][1]),
                          "r"(af[mf][2]), "r"(af[mf][3]),
                          "r"(bf[nf][0]), "r"(bf[nf][1]));
        }
        __syncthreads();
    }

    // epilogue: bias + sigmoid + tf32 round, write PHI row-major
#pragma unroll
    for (int mf = 0; mf < 4; mf++) {
        int r0 = m0 + wm * 64 + mf * 16 + lr;
#pragma unroll
        for (int nf = 0; nf < 8; nf++) {
            int c = n0 + wn * 64 + nf * 8 + lc * 2;
            float b0v = __ldg(bias + c), b1v = __ldg(bias + c + 1);
            float v0 = tf32r(1.f / (1.f + __expf(-(acc[mf][nf][0] + b0v))));
            float v1 = tf32r(1.f / (1.f + __expf(-(acc[mf][nf][1] + b1v))));
            float v2 = tf32r(1.f / (1.f + __expf(-(acc[mf][nf][2] + b0v))));
            float v3 = tf32r(1.f / (1.f + __expf(-(acc[mf][nf][3] + b1v))));
            *reinterpret_cast<float2*>(C + (size_t)r0 * HIDDEN + c) = make_float2(v0, v1);
            *reinterpret_cast<float2*>(C + (size_t)(r0 + 8) * HIDDEN + c) = make_float2(v2, v3);
        }
    }
}

// ---------------------------------------------------------------------------
// GEMM2 (round-1 proven kernel): logits = PHI @ Wh + bh, NGUARD for N=1000.
// ---------------------------------------------------------------------------
#define BM 128
#define BN 128
#define BK 32
#define AS_STRIDE 36
#define BS_STRIDE 136
#define AS_SIZE (BM * AS_STRIDE)
#define BS_SIZE (BK * BS_STRIDE)
#define SMEM2_BYTES (2 * (AS_SIZE + BS_SIZE) * 4)

__device__ __forceinline__ void cp_async16p(uint32_t saddr, const void* gptr, int src_bytes) {
    asm volatile("cp.async.cg.shared.global [%0], [%1], 16, %2;\n"
                 :: "r"(saddr), "l"(gptr), "r"(src_bytes));
}

__global__ void __launch_bounds__(256, 2)
gemm2_kernel(const float* __restrict__ A,
             const float* __restrict__ B,
             const float* __restrict__ bias,
             float* __restrict__ C,
             int K, int Nreal) {
    extern __shared__ float smem[];
    float* As = smem;
    float* Bs = smem + 2 * AS_SIZE;

    const int tid  = threadIdx.x;
    const int lane = tid & 31;
    const int warp = tid >> 5;
    const int wm   = warp & 1;
    const int wn   = warp >> 1;

    const int bm0 = blockIdx.y * BM;
    const int bn0 = blockIdx.x * BN;

    const int a_row  = tid >> 3;
    const int a_col  = (tid & 7) * 4;
    const int b_rowt = tid >> 5;
    const int b_colt = (tid & 31) * 4;

    float acc[4][4][4];
#pragma unroll
    for (int i = 0; i < 4; i++)
#pragma unroll
        for (int j = 0; j < 4; j++)
#pragma unroll
            for (int k = 0; k < 4; k++) acc[i][j][k] = 0.f;

    const int KT = K / BK;

    auto load_stage = [&](int kt, int stage) {
        float* as = As + stage * AS_SIZE;
        float* bs = Bs + stage * BS_SIZE;
        const float* Ag = A + (size_t)(bm0 + a_row) * K + kt * BK + a_col;
#pragma unroll
        for (int i = 0; i < 4; i++) {
            uint32_t sa = (uint32_t)__cvta_generic_to_shared(
                as + (a_row + i * 32) * AS_STRIDE + a_col);
            cp_async16p(sa, Ag + (size_t)i * 32 * K, 16);
        }
#pragma unroll
        for (int i = 0; i < 4; i++) {
            int row = b_rowt + i * 8;
            int col = bn0 + b_colt;
            const float* gp = B + (size_t)(kt * BK + row) * Nreal + col;
            int sz = 16;
            if (col >= Nreal) { gp = B; sz = 0; }
            uint32_t sb = (uint32_t)__cvta_generic_to_shared(
                bs + row * BS_STRIDE + b_colt);
            cp_async16p(sb, gp, sz);
        }
        asm volatile("cp.async.commit_group;\n");
    };

    load_stage(0, 0);

    for (int kt = 0; kt < KT; kt++) {
        int stage = kt & 1;
        if (kt + 1 < KT) {
            load_stage(kt + 1, stage ^ 1);
            asm volatile("cp.async.wait_group 1;\n");
        } else {
            asm volatile("cp.async.wait_group 0;\n");
        }
        __syncthreads();

        const float* as = As + stage * AS_SIZE;
        const float* bs = Bs + stage * BS_SIZE;

#pragma unroll
        for (int ks = 0; ks < 4; ks++) {
            const int kk = ks * 8 + (lane & 3);
            uint32_t af[4][4];
            uint32_t bf[4][2];
            const int r0base = wm * 64 + (lane >> 2);
#pragma unroll
            for (int mf = 0; mf < 4; mf++) {
                int r0 = r0base + mf * 16;
                af[mf][0] = __float_as_uint(as[r0 * AS_STRIDE + kk]);
                af[mf][1] = __float_as_uint(as[(r0 + 8) * AS_STRIDE + kk]);
                af[mf][2] = __float_as_uint(as[r0 * AS_STRIDE + kk + 4]);
                af[mf][3] = __float_as_uint(as[(r0 + 8) * AS_STRIDE + kk + 4]);
            }
            const int cb0 = wn * 32 + (lane >> 2);
#pragma unroll
            for (int nf = 0; nf < 4; nf++) {
                int cb = cb0 + nf * 8;
                bf[nf][0] = f2tf32(bs[kk * BS_STRIDE + cb]);
                bf[nf][1] = f2tf32(bs[(kk + 4) * BS_STRIDE + cb]);
            }
#pragma unroll
            for (int mf = 0; mf < 4; mf++)
#pragma unroll
                for (int nf = 0; nf < 4; nf++)
                    asm volatile(
                        "mma.sync.aligned.m16n8k8.row.col.f32.tf32.tf32.f32 "
                        "{%0,%1,%2,%3}, {%4,%5,%6,%7}, {%8,%9}, {%0,%1,%2,%3};\n"
                        : "+f"(acc[mf][nf][0]), "+f"(acc[mf][nf][1]),
                          "+f"(acc[mf][nf][2]), "+f"(acc[mf][nf][3])
                        : "r"(af[mf][0]), "r"(af[mf][1]),
                          "r"(af[mf][2]), "r"(af[mf][3]),
                          "r"(bf[nf][0]), "r"(bf[nf][1]));
        }
        __syncthreads();
    }

#pragma unroll
    for (int mf = 0; mf < 4; mf++) {
        int r0 = bm0 + wm * 64 + mf * 16 + (lane >> 2);
#pragma unroll
        for (int nf = 0; nf < 4; nf++) {
            int c0 = bn0 + wn * 32 + nf * 8 + (lane & 3) * 2;
#pragma unroll
            for (int half = 0; half < 2; half++) {
                int r = r0 + half * 8;
#pragma unroll
                for (int e = 0; e < 2; e++) {
                    int c = c0 + e;
                    if (c >= Nreal) continue;
                    float v = acc[mf][nf][half * 2 + e] + __ldg(bias + c);
                    C[(size_t)r * Nreal + c] = v;
                }
            }
        }
    }
}

// ---------------------------------------------------------------------------
// Launch
// ---------------------------------------------------------------------------
extern "C" void kernel_launch(void* const* d_in, const int* in_sizes, int n_in,
                              void* d_out, int out_size) {
    const float* x       = (const float*)d_in[0];
    const float* centers = (const float*)d_in[1];
    const float* scales  = (const float*)d_in[2];
    const float* Wb      = (const float*)d_in[3];
    const float* bb      = (const float*)d_in[4];
    const float* Wh      = (const float*)d_in[5];
    const float* bh      = (const float*)d_in[6];
    float* out = (float*)d_out;

    float *F, *PHI;
    cudaGetSymbolAddress((void**)&F, g_F);
    cudaGetSymbolAddress((void**)&PHI, g_PHI);

    cudaFuncSetAttribute(gemm1_kernel,
                         cudaFuncAttributeMaxDynamicSharedMemorySize, G1_SMEM);
    cudaFuncSetAttribute(gemm2_kernel,
                         cudaFuncAttributeMaxDynamicSharedMemorySize, SMEM2_BYTES);

    // 1) feats -> packed F (pre-rounded tf32)
    {
        int chunks = BATCH * KDIM / 4;     // 16.77M
        feats_packed_kernel<<<chunks / 256, 256>>>(x, centers, scales, F);
    }
    // 2) GEMM1: PHI = sigmoid(F @ Wb + bb)
    {
        dim3 grid(HIDDEN / 256, BATCH / 128);   // (16, 32)
        gemm1_kernel<<<grid, 256, G1_SMEM>>>(F, Wb, bb, PHI);
    }
    // 3) GEMM2: out = PHI @ Wh + bh
    {
        dim3 grid(NPAD / BN, BATCH / BM);       // (8, 32)
        gemm2_kernel<<<grid, 256, SMEM2_BYTES>>>(PHI, Wh, bh, out, HIDDEN, CLASSES);
    }
}

// round 4
// speedup vs baseline: 2.0908x; 2.0018x over previous
#include <cuda_runtime.h>
#include <cuda_fp16.h>
#include <cstdint>

// ---------------------------------------------------------------------------
// KANClassifier, fp16 mma.sync path (tcgen05 blocked by compute_103 target).
// All GEMM operands pre-packed in mma m16n8k16 fragment order -> every
// fragment load is one LDS.128, no cvt in the mainloop, HMMA-bound.
//   feats -> F packed fp16 (A-layout)
//   Wb/Wh -> packed fp16 (B-layout), Wh zero-padded to 1024 cols
//   GEMM1 128x256: PHI = sigmoid(F@Wb+bb), epilogue writes PHI packed (A-layout)
//   GEMM2 128x256: out = PHI@Wh+bh (fp32, N=1000 guard)
// ---------------------------------------------------------------------------

#define BATCH   4096
#define IN_DIM  1024
#define KDIM    16384
#define HIDDEN  4096
#define CLASSES 1000
#define NPAD    1024

#define KT1 (KDIM / 32)     // 512 k-tiles for GEMM1
#define KT2 (HIDDEN / 32)   // 128 k-tiles for GEMM2

// device scratch (uint4 = one 16B chunk = 8 halfs)
__device__ __align__(1024) uint4 g_F  [(size_t)BATCH * KDIM / 8];    // 128MB
__device__ __align__(1024) uint4 g_PHI[(size_t)BATCH * HIDDEN / 8];  // 32MB
__device__ __align__(1024) uint4 g_WbP[(size_t)KDIM * HIDDEN / 8];   // 128MB
__device__ __align__(1024) uint4 g_WhP[(size_t)HIDDEN * NPAD / 8];   // 8MB

__device__ __forceinline__ uint32_t pack_half2(float a, float b) {
    __half2 h = __floats2half2_rn(a, b);
    return *reinterpret_cast<uint32_t*>(&h);
}
__device__ __forceinline__ float fast_tanh(float v) {
    // 1 - 2/(e^{2v}+1); handles +-inf correctly via __expf saturation
    return 1.f - 2.f / (__expf(2.f * v) + 1.f);
}
__device__ __forceinline__ void cp_async16(uint32_t saddr, const void* gptr) {
    asm volatile("cp.async.cg.shared.global [%0], [%1], 16;\n" :: "r"(saddr), "l"(gptr));
}

// ---------------------------------------------------------------------------
// A-packed layout (tile = 128 rows x 32 k, 512 chunks):
//   chunk = ks*256 + grp*32 + lane;  lane = rlo*4 + klane
//   r = grp*16 + rlo (+8 inside), k0 = ks*16 + klane*2 (+1,+8,+9 inside)
//   halves: (r,k0)(r,k0+1) | (r+8,k0)(r+8,k0+1) | (r,k0+8)(r,k0+9) | (r+8,k0+8)(r+8,k0+9)
// B-packed layout (tile = 32 k x 256 n, 1024 chunks):
//   chunk = (ks*16 + npair)*32 + lane;  c = npair*16 + (lane>>2), k0 = ks*16+(lane&3)*2
//   halves: (k0,c)(k0+1,c) | (k0+8,c)(k0+9,c) | (k0,c+8)(k0+1,c+8) | (k0+8,c+8)(k0+9,c+8)
// ---------------------------------------------------------------------------

// Kernel 1: tanh basis -> g_F packed (one thread per 16B chunk, 8 tanh)
__global__ void feats_packed_kernel(const float* __restrict__ x,
                                    const float* __restrict__ centers,
                                    const float* __restrict__ scales,
                                    uint4* __restrict__ F) {
    int g = blockIdx.x * blockDim.x + threadIdx.x;
    int lane = g & 31, grp = (g >> 5) & 7, ks = (g >> 8) & 1;
    int kt = (g >> 9) & (KT1 - 1), mt = g >> 18;
    int rlo = lane >> 2, klane = lane & 3;
    int r = mt * 128 + grp * 16 + rlo;
    int d = kt * 2 + ks;
    int j0 = klane * 2;

    float xv0 = __ldg(x + (size_t)r * IN_DIM + d);
    float xv1 = __ldg(x + (size_t)(r + 8) * IN_DIM + d);
    const float* cd = centers + d * 16;
    const float* sd = scales + d * 16;
    float c0 = __ldg(cd + j0), c1 = __ldg(cd + j0 + 1);
    float c8 = __ldg(cd + j0 + 8), c9 = __ldg(cd + j0 + 9);
    float s0 = __ldg(sd + j0), s1 = __ldg(sd + j0 + 1);
    float s8 = __ldg(sd + j0 + 8), s9 = __ldg(sd + j0 + 9);

    uint4 o;
    o.x = pack_half2(fast_tanh((xv0 - c0) * s0), fast_tanh((xv0 - c1) * s1));
    o.y = pack_half2(fast_tanh((xv1 - c0) * s0), fast_tanh((xv1 - c1) * s1));
    o.z = pack_half2(fast_tanh((xv0 - c8) * s8), fast_tanh((xv0 - c9) * s9));
    o.w = pack_half2(fast_tanh((xv1 - c8) * s8), fast_tanh((xv1 - c9) * s9));
    F[g] = o;
}

// Kernel 2: fp32 W [K][Nsrc] -> packed fp16 B-layout (pad cols >= Nsrc with 0)
__global__ void convert_pack_b_kernel(const float* __restrict__ W,
                                      uint4* __restrict__ out,
                                      int KT, int Nsrc) {
    int g = blockIdx.x * blockDim.x + threadIdx.x;
    int lane = g & 31, npair = (g >> 5) & 15, ks = (g >> 9) & 1;
    int tile = g >> 10;
    int kt = tile % KT, nt = tile / KT;
    int k0 = kt * 32 + ks * 16 + (lane & 3) * 2;
    int c  = nt * 256 + npair * 16 + (lane >> 2);
    int c8 = c + 8;

    const float* w0 = W + (size_t)k0 * Nsrc;
    float a00 = 0.f, a10 = 0.f, a80 = 0.f, a90 = 0.f;
    float a08 = 0.f, a18 = 0.f, a88 = 0.f, a98 = 0.f;
    if (c < Nsrc) {
        a00 = __ldg(w0 + c);
        a10 = __ldg(w0 + Nsrc + c);
        a80 = __ldg(w0 + (size_t)8 * Nsrc + c);
        a90 = __ldg(w0 + (size_t)9 * Nsrc + c);
    }
    if (c8 < Nsrc) {
        a08 = __ldg(w0 + c8);
        a18 = __ldg(w0 + Nsrc + c8);
        a88 = __ldg(w0 + (size_t)8 * Nsrc + c8);
        a98 = __ldg(w0 + (size_t)9 * Nsrc + c8);
    }
    uint4 o;
    o.x = pack_half2(a00, a10);
    o.y = pack_half2(a80, a90);
    o.z = pack_half2(a08, a18);
    o.w = pack_half2(a88, a98);
    out[g] = o;
}

// ---------------------------------------------------------------------------
// Unified fp16 GEMM: 128x256x32 block, 8 warps (2M x 4N), warp 64x64,
// 4-stage cp.async. A/B pre-packed. Epilogue: bias (+sigmoid) and either
// packed-fp16 output (A-layout for next GEMM) or fp32 row-major w/ N guard.
// ---------------------------------------------------------------------------
#define STAGES 4
#define A_CH 512       // uint4 chunks per A stage (8KB)
#define B_CH 1024      // uint4 chunks per B stage (16KB)
#define SMEM_BYTES (STAGES * (A_CH + B_CH) * 16)   // 96KB

__device__ __forceinline__ void mma16816(float* d, const uint4& a,
                                         uint32_t b0, uint32_t b1) {
    asm volatile(
        "mma.sync.aligned.m16n8k16.row.col.f32.f16.f16.f32 "
        "{%0,%1,%2,%3}, {%4,%5,%6,%7}, {%8,%9}, {%0,%1,%2,%3};\n"
        : "+f"(d[0]), "+f"(d[1]), "+f"(d[2]), "+f"(d[3])
        : "r"(a.x), "r"(a.y), "r"(a.z), "r"(a.w), "r"(b0), "r"(b1));
}

template <bool SIGMOID, bool PACKED_OUT>
__global__ void __launch_bounds__(256, 1)
gemm_fp16_kernel(const uint4* __restrict__ Apk,
                 const uint4* __restrict__ Bpk,
                 const float* __restrict__ bias,
                 void* __restrict__ outp,
                 int KT, int KTout, int Nreal) {
    extern __shared__ uint4 sm4[];
    uint4* As = sm4;                    // [STAGES][A_CH]
    uint4* Bs = sm4 + STAGES * A_CH;    // [STAGES][B_CH]

    const int tid = threadIdx.x;
    const int lane = tid & 31;
    const int warp = tid >> 5;
    const int wm = warp & 1, wn = warp >> 1;
    const int lr = lane >> 2, lc = lane & 3;
    const int mt = blockIdx.y, nt = blockIdx.x;
    const int m0 = mt * 128, n0 = nt * 256;

    float acc[4][8][4];
#pragma unroll
    for (int i = 0; i < 4; i++)
#pragma unroll
        for (int j = 0; j < 8; j++)
#pragma unroll
            for (int k = 0; k < 4; k++) acc[i][j][k] = 0.f;

    auto load_stage = [&](int kt, int s) {
        const uint4* ag = Apk + ((size_t)mt * KT + kt) * A_CH;
        uint4* as = As + s * A_CH;
#pragma unroll
        for (int p = 0; p < 2; p++) {
            int ci = tid + p * 256;
            cp_async16((uint32_t)__cvta_generic_to_shared(as + ci), ag + ci);
        }
        const uint4* bg = Bpk + ((size_t)nt * KT + kt) * B_CH;
        uint4* bs = Bs + s * B_CH;
#pragma unroll
        for (int p = 0; p < 4; p++) {
            int ci = tid + p * 256;
            cp_async16((uint32_t)__cvta_generic_to_shared(bs + ci), bg + ci);
        }
        asm volatile("cp.async.commit_group;\n");
    };

    load_stage(0, 0);
    load_stage(1, 1);
    load_stage(2, 2);

    for (int kt = 0; kt < KT; kt++) {
        asm volatile("cp.async.wait_group 2;\n");
        __syncthreads();
        if (kt + 3 < KT) load_stage(kt + 3, (kt + 3) & (STAGES - 1));
        else asm volatile("cp.async.commit_group;\n");

        const int s = kt & (STAGES - 1);
        const uint4* as = As + s * A_CH;
        const uint4* bs = Bs + s * B_CH;

#pragma unroll
        for (int ks = 0; ks < 2; ks++) {
            uint4 av[4];
#pragma unroll
            for (int mf = 0; mf < 4; mf++)
                av[mf] = as[ks * 256 + (wm * 4 + mf) * 32 + lane];
            uint4 bv[4];
#pragma unroll
            for (int np = 0; np < 4; np++)
                bv[np] = bs[(ks * 16 + wn * 4 + np) * 32 + lane];
#pragma unroll
            for (int mf = 0; mf < 4; mf++)
#pragma unroll
                for (int np = 0; np < 4; np++) {
                    mma16816(acc[mf][2 * np],     av[mf], bv[np].x, bv[np].y);
                    mma16816(acc[mf][2 * np + 1], av[mf], bv[np].z, bv[np].w);
                }
        }
        __syncthreads();
    }

    // ------------------ epilogue ------------------
#pragma unroll
    for (int mf = 0; mf < 4; mf++) {
        const int r0 = m0 + wm * 64 + mf * 16 + lr;
        const int grp = wm * 4 + mf;
#pragma unroll
        for (int npi = 0; npi < 4; npi++) {
            const int nf = npi * 2;
            const int c = n0 + wn * 64 + nf * 8 + lc * 2;
            float b0 = 0.f, b1 = 0.f, b2 = 0.f, b3 = 0.f;
            if (!PACKED_OUT) {
                if (c < Nreal)     b0 = __ldg(bias + c);
                if (c + 1 < Nreal) b1 = __ldg(bias + c + 1);
                if (c + 8 < Nreal) b2 = __ldg(bias + c + 8);
                if (c + 9 < Nreal) b3 = __ldg(bias + c + 9);
            } else {
                b0 = __ldg(bias + c);     b1 = __ldg(bias + c + 1);
                b2 = __ldg(bias + c + 8); b3 = __ldg(bias + c + 9);
            }
            float v00 = acc[mf][nf][0] + b0,     v01 = acc[mf][nf][1] + b1;
            float v10 = acc[mf][nf][2] + b0,     v11 = acc[mf][nf][3] + b1;
            float v20 = acc[mf][nf + 1][0] + b2, v21 = acc[mf][nf + 1][1] + b3;
            float v30 = acc[mf][nf + 1][2] + b2, v31 = acc[mf][nf + 1][3] + b3;
            if (SIGMOID) {
                v00 = 1.f / (1.f + __expf(-v00)); v01 = 1.f / (1.f + __expf(-v01));
                v10 = 1.f / (1.f + __expf(-v10)); v11 = 1.f / (1.f + __expf(-v11));
                v20 = 1.f / (1.f + __expf(-v20)); v21 = 1.f / (1.f + __expf(-v21));
                v30 = 1.f / (1.f + __expf(-v30)); v31 = 1.f / (1.f + __expf(-v31));
            }
            if (PACKED_OUT) {
                // write as A-packed fp16 chunk for the next GEMM
                int kt2 = c >> 5;
                int ks2 = npi & 1;
                size_t chunk = ((size_t)mt * KTout + kt2) * A_CH
                             + ks2 * 256 + grp * 32 + lane;
                uint4 o;
                o.x = pack_half2(v00, v01);
                o.y = pack_half2(v10, v11);
                o.z = pack_half2(v20, v21);
                o.w = pack_half2(v30, v31);
                reinterpret_cast<uint4*>(outp)[chunk] = o;
            } else {
                float* C = reinterpret_cast<float*>(outp);
                if (c < Nreal)     C[(size_t)r0 * Nreal + c] = v00;
                if (c + 1 < Nreal) C[(size_t)r0 * Nreal + c + 1] = v01;
                if (c < Nreal)     C[(size_t)(r0 + 8) * Nreal + c] = v10;
                if (c + 1 < Nreal) C[(size_t)(r0 + 8) * Nreal + c + 1] = v11;
                if (c + 8 < Nreal) C[(size_t)r0 * Nreal + c + 8] = v20;
                if (c + 9 < Nreal) C[(size_t)r0 * Nreal + c + 9] = v21;
                if (c + 8 < Nreal) C[(size_t)(r0 + 8) * Nreal + c + 8] = v30;
                if (c + 9 < Nreal) C[(size_t)(r0 + 8) * Nreal + c + 9] = v31;
            }
        }
    }
}

// ---------------------------------------------------------------------------
// Launch
// ---------------------------------------------------------------------------
extern "C" void kernel_launch(void* const* d_in, const int* in_sizes, int n_in,
                              void* d_out, int out_size) {
    const float* x       = (const float*)d_in[0];
    const float* centers = (const float*)d_in[1];
    const float* scales  = (const float*)d_in[2];
    const float* Wb      = (const float*)d_in[3];
    const float* bb      = (const float*)d_in[4];
    const float* Wh      = (const float*)d_in[5];
    const float* bh      = (const float*)d_in[6];
    float* out = (float*)d_out;

    uint4 *F, *PHI, *WbP, *WhP;
    cudaGetSymbolAddress((void**)&F, g_F);
    cudaGetSymbolAddress((void**)&PHI, g_PHI);
    cudaGetSymbolAddress((void**)&WbP, g_WbP);
    cudaGetSymbolAddress((void**)&WhP, g_WhP);

    cudaFuncSetAttribute((const void*)gemm_fp16_kernel<true, true>,
                         cudaFuncAttributeMaxDynamicSharedMemorySize, SMEM_BYTES);
    cudaFuncSetAttribute((const void*)gemm_fp16_kernel<false, false>,
                         cudaFuncAttributeMaxDynamicSharedMemorySize, SMEM_BYTES);

    // 1) feats -> packed fp16 F
    {
        size_t chunks = (size_t)BATCH * KDIM / 8;   // 8.39M
        feats_packed_kernel<<<(int)(chunks / 256), 256>>>(x, centers, scales, F);
    }
    // 2) pack Wb, Wh
    {
        size_t cb = (size_t)KDIM * HIDDEN / 8;      // 8.39M
        convert_pack_b_kernel<<<(int)(cb / 256), 256>>>(Wb, WbP, KT1, HIDDEN);
        size_t ch = (size_t)HIDDEN * NPAD / 8;      // 524K
        convert_pack_b_kernel<<<(int)(ch / 256), 256>>>(Wh, WhP, KT2, CLASSES);
    }
    // 3) GEMM1: PHI(packed) = sigmoid(F @ Wb + bb)
    {
        dim3 grid(HIDDEN / 256, BATCH / 128);       // (16, 32)
        gemm_fp16_kernel<true, true><<<grid, 256, SMEM_BYTES>>>(
            F, WbP, bb, PHI, KT1, KT2, HIDDEN);
    }
    // 4) GEMM2: out = PHI @ Wh + bh (fp32, N guard)
    {
        dim3 grid(NPAD / 256, BATCH / 128);         // (4, 32)
        gemm_fp16_kernel<false, false><<<grid, 256, SMEM_BYTES>>>(
            PHI, WhP, bh, out, KT2, 0, CLASSES);
    }
}

// round 5
// speedup vs baseline: 2.1604x; 1.0333x over previous
#include <cuda_runtime.h>
#include <cuda_fp16.h>
#include <cstdint>

// ---------------------------------------------------------------------------
// KANClassifier, fp16 mma.sync path. Round 5: BK=64 stages (half the
// barriers), 4-stage 192KB smem pipeline, supertile rasterization, MUFU tanh.
// ---------------------------------------------------------------------------

#define BATCH   4096
#define IN_DIM  1024
#define KDIM    16384
#define HIDDEN  4096
#define CLASSES 1000
#define NPAD    1024

#define KT1 (KDIM / 32)     // 512 single k-tiles (GEMM1)
#define KT2 (HIDDEN / 32)   // 128 single k-tiles (GEMM2)

__device__ __align__(1024) uint4 g_F  [(size_t)BATCH * KDIM / 8];
__device__ __align__(1024) uint4 g_PHI[(size_t)BATCH * HIDDEN / 8];
__device__ __align__(1024) uint4 g_WbP[(size_t)KDIM * HIDDEN / 8];
__device__ __align__(1024) uint4 g_WhP[(size_t)HIDDEN * NPAD / 8];

__device__ __forceinline__ uint32_t pack_half2(float a, float b) {
    __half2 h = __floats2half2_rn(a, b);
    return *reinterpret_cast<uint32_t*>(&h);
}
__device__ __forceinline__ float mufu_tanh(float v) {
    float r;
    asm("tanh.approx.f32 %0, %1;" : "=f"(r) : "f"(v));
    return r;
}
__device__ __forceinline__ void cp_async16(uint32_t saddr, const void* gptr) {
    asm volatile("cp.async.cg.shared.global [%0], [%1], 16;\n" :: "r"(saddr), "l"(gptr));
}

// ---------------------------------------------------------------------------
// Kernel 1: tanh basis -> g_F packed fp16 (A fragment layout)
// ---------------------------------------------------------------------------
__global__ void feats_packed_kernel(const float* __restrict__ x,
                                    const float* __restrict__ centers,
                                    const float* __restrict__ scales,
                                    uint4* __restrict__ F) {
    int g = blockIdx.x * blockDim.x + threadIdx.x;
    int lane = g & 31, grp = (g >> 5) & 7, ks = (g >> 8) & 1;
    int kt = (g >> 9) & (KT1 - 1), mt = g >> 18;
    int rlo = lane >> 2, klane = lane & 3;
    int r = mt * 128 + grp * 16 + rlo;
    int d = kt * 2 + ks;
    int j0 = klane * 2;

    float xv0 = __ldg(x + (size_t)r * IN_DIM + d);
    float xv1 = __ldg(x + (size_t)(r + 8) * IN_DIM + d);
    const float* cd = centers + d * 16;
    const float* sd = scales + d * 16;
    float c0 = __ldg(cd + j0), c1 = __ldg(cd + j0 + 1);
    float c8 = __ldg(cd + j0 + 8), c9 = __ldg(cd + j0 + 9);
    float s0 = __ldg(sd + j0), s1 = __ldg(sd + j0 + 1);
    float s8 = __ldg(sd + j0 + 8), s9 = __ldg(sd + j0 + 9);

    uint4 o;
    o.x = pack_half2(mufu_tanh((xv0 - c0) * s0), mufu_tanh((xv0 - c1) * s1));
    o.y = pack_half2(mufu_tanh((xv1 - c0) * s0), mufu_tanh((xv1 - c1) * s1));
    o.z = pack_half2(mufu_tanh((xv0 - c8) * s8), mufu_tanh((xv0 - c9) * s9));
    o.w = pack_half2(mufu_tanh((xv1 - c8) * s8), mufu_tanh((xv1 - c9) * s9));
    F[g] = o;
}

// Kernel 2: fp32 W [K][Nsrc] -> packed fp16 B-layout (pad cols >= Nsrc)
__global__ void convert_pack_b_kernel(const float* __restrict__ W,
                                      uint4* __restrict__ out,
                                      int KT, int Nsrc) {
    int g = blockIdx.x * blockDim.x + threadIdx.x;
    int lane = g & 31, npair = (g >> 5) & 15, ks = (g >> 9) & 1;
    int tile = g >> 10;
    int kt = tile % KT, nt = tile / KT;
    int k0 = kt * 32 + ks * 16 + (lane & 3) * 2;
    int c  = nt * 256 + npair * 16 + (lane >> 2);
    int c8 = c + 8;

    const float* w0 = W + (size_t)k0 * Nsrc;
    float a00 = 0.f, a10 = 0.f, a80 = 0.f, a90 = 0.f;
    float a08 = 0.f, a18 = 0.f, a88 = 0.f, a98 = 0.f;
    if (c < Nsrc) {
        a00 = __ldg(w0 + c);
        a10 = __ldg(w0 + Nsrc + c);
        a80 = __ldg(w0 + (size_t)8 * Nsrc + c);
        a90 = __ldg(w0 + (size_t)9 * Nsrc + c);
    }
    if (c8 < Nsrc) {
        a08 = __ldg(w0 + c8);
        a18 = __ldg(w0 + Nsrc + c8);
        a88 = __ldg(w0 + (size_t)8 * Nsrc + c8);
        a98 = __ldg(w0 + (size_t)9 * Nsrc + c8);
    }
    uint4 o;
    o.x = pack_half2(a00, a10);
    o.y = pack_half2(a80, a90);
    o.z = pack_half2(a08, a18);
    o.w = pack_half2(a88, a98);
    out[g] = o;
}

// ---------------------------------------------------------------------------
// fp16 GEMM: 128x256 block, BK=64 per stage, 4 stages (192KB), 8 warps
// (2M x 4N, warp 64x64). Supertile raster (GRP=8 along M).
// ---------------------------------------------------------------------------
#define STAGES 4
#define A_CH 1024      // uint4 per A stage (16KB = 128r x 64k fp16)
#define B_CH 2048      // uint4 per B stage (32KB = 64k x 256n fp16)
#define SMEM_BYTES (STAGES * (A_CH + B_CH) * 16)   // 192KB

__device__ __forceinline__ void mma16816(float* d, const uint4& a,
                                         uint32_t b0, uint32_t b1) {
    asm volatile(
        "mma.sync.aligned.m16n8k16.row.col.f32.f16.f16.f32 "
        "{%0,%1,%2,%3}, {%4,%5,%6,%7}, {%8,%9}, {%0,%1,%2,%3};\n"
        : "+f"(d[0]), "+f"(d[1]), "+f"(d[2]), "+f"(d[3])
        : "r"(a.x), "r"(a.y), "r"(a.z), "r"(a.w), "r"(b0), "r"(b1));
}

template <bool SIGMOID, bool PACKED_OUT>
__global__ void __launch_bounds__(256, 1)
gemm_fp16_kernel(const uint4* __restrict__ Apk,
                 const uint4* __restrict__ Bpk,
                 const float* __restrict__ bias,
                 void* __restrict__ outp,
                 int KTs,        // single k-tile count (addressing)
                 int KTout,      // single k-tile count of downstream GEMM
                 int Nreal,
                 int nTiles) {   // # of 256-wide n tiles
    extern __shared__ uint4 sm4[];
    uint4* As = sm4;
    uint4* Bs = sm4 + STAGES * A_CH;

    const int tid = threadIdx.x;
    const int lane = tid & 31;
    const int warp = tid >> 5;
    const int wm = warp & 1, wn = warp >> 1;
    const int lr = lane >> 2, lc = lane & 3;

    // supertile raster: GRP m-tiles per column, nt-major within group
    const int GRP = 8;
    int per = GRP * nTiles;
    int mt = (blockIdx.x / per) * GRP + (blockIdx.x % per) % GRP;
    int nt = (blockIdx.x % per) / GRP;
    const int m0 = mt * 128, n0 = nt * 256;
    const int KT2c = KTs / 2;   // double-ktile count

    float acc[4][8][4];
#pragma unroll
    for (int i = 0; i < 4; i++)
#pragma unroll
        for (int j = 0; j < 8; j++)
#pragma unroll
            for (int k = 0; k < 4; k++) acc[i][j][k] = 0.f;

    auto load_stage = [&](int kt2, int s) {
        const uint4* ag = Apk + ((size_t)mt * KTs + kt2 * 2) * 512;
        uint4* as = As + s * A_CH;
#pragma unroll
        for (int p = 0; p < 4; p++) {
            int ci = tid + p * 256;
            cp_async16((uint32_t)__cvta_generic_to_shared(as + ci), ag + ci);
        }
        const uint4* bg = Bpk + ((size_t)nt * KTs + kt2 * 2) * 1024;
        uint4* bs = Bs + s * B_CH;
#pragma unroll
        for (int p = 0; p < 8; p++) {
            int ci = tid + p * 256;
            cp_async16((uint32_t)__cvta_generic_to_shared(bs + ci), bg + ci);
        }
        asm volatile("cp.async.commit_group;\n");
    };

    load_stage(0, 0);
    load_stage(1, 1);
    load_stage(2, 2);

    for (int kt2 = 0; kt2 < KT2c; kt2++) {
        asm volatile("cp.async.wait_group 2;\n");
        __syncthreads();
        if (kt2 + 3 < KT2c) load_stage(kt2 + 3, (kt2 + 3) & (STAGES - 1));
        else asm volatile("cp.async.commit_group;\n");

        const int s = kt2 & (STAGES - 1);
        const uint4* as = As + s * A_CH;
        const uint4* bs = Bs + s * B_CH;

#pragma unroll
        for (int ksg = 0; ksg < 4; ksg++) {      // 4 x k16 within BK=64
            const int half = ksg >> 1, ks = ksg & 1;
            uint4 av[4];
#pragma unroll
            for (int mf = 0; mf < 4; mf++)
                av[mf] = as[half * 512 + ks * 256 + (wm * 4 + mf) * 32 + lane];
            uint4 bv[4];
#pragma unroll
            for (int np = 0; np < 4; np++)
                bv[np] = bs[half * 1024 + (ks * 16 + wn * 4 + np) * 32 + lane];
#pragma unroll
            for (int mf = 0; mf < 4; mf++)
#pragma unroll
                for (int np = 0; np < 4; np++) {
                    mma16816(acc[mf][2 * np],     av[mf], bv[np].x, bv[np].y);
                    mma16816(acc[mf][2 * np + 1], av[mf], bv[np].z, bv[np].w);
                }
        }
        __syncthreads();
    }

    // ------------------ epilogue ------------------
#pragma unroll
    for (int mf = 0; mf < 4; mf++) {
        const int r0 = m0 + wm * 64 + mf * 16 + lr;
        const int grp = wm * 4 + mf;
#pragma unroll
        for (int npi = 0; npi < 4; npi++) {
            const int nf = npi * 2;
            const int c = n0 + wn * 64 + nf * 8 + lc * 2;
            float b0 = 0.f, b1 = 0.f, b2 = 0.f, b3 = 0.f;
            if (!PACKED_OUT) {
                if (c < Nreal)     b0 = __ldg(bias + c);
                if (c + 1 < Nreal) b1 = __ldg(bias + c + 1);
                if (c + 8 < Nreal) b2 = __ldg(bias + c + 8);
                if (c + 9 < Nreal) b3 = __ldg(bias + c + 9);
            } else {
                b0 = __ldg(bias + c);     b1 = __ldg(bias + c + 1);
                b2 = __ldg(bias + c + 8); b3 = __ldg(bias + c + 9);
            }
            float v00 = acc[mf][nf][0] + b0,     v01 = acc[mf][nf][1] + b1;
            float v10 = acc[mf][nf][2] + b0,     v11 = acc[mf][nf][3] + b1;
            float v20 = acc[mf][nf + 1][0] + b2, v21 = acc[mf][nf + 1][1] + b3;
            float v30 = acc[mf][nf + 1][2] + b2, v31 = acc[mf][nf + 1][3] + b3;
            if (SIGMOID) {
                v00 = 1.f / (1.f + __expf(-v00)); v01 = 1.f / (1.f + __expf(-v01));
                v10 = 1.f / (1.f + __expf(-v10)); v11 = 1.f / (1.f + __expf(-v11));
                v20 = 1.f / (1.f + __expf(-v20)); v21 = 1.f / (1.f + __expf(-v21));
                v30 = 1.f / (1.f + __expf(-v30)); v31 = 1.f / (1.f + __expf(-v31));
            }
            if (PACKED_OUT) {
                int kt2 = c >> 5;
                int ks2 = npi & 1;
                size_t chunk = ((size_t)mt * KTout + kt2) * 512
                             + ks2 * 256 + grp * 32 + lane;
                uint4 o;
                o.x = pack_half2(v00, v01);
                o.y = pack_half2(v10, v11);
                o.z = pack_half2(v20, v21);
                o.w = pack_half2(v30, v31);
                reinterpret_cast<uint4*>(outp)[chunk] = o;
            } else {
                float* C = reinterpret_cast<float*>(outp);
                if (c < Nreal)     C[(size_t)r0 * Nreal + c] = v00;
                if (c + 1 < Nreal) C[(size_t)r0 * Nreal + c + 1] = v01;
                if (c < Nreal)     C[(size_t)(r0 + 8) * Nreal + c] = v10;
                if (c + 1 < Nreal) C[(size_t)(r0 + 8) * Nreal + c + 1] = v11;
                if (c + 8 < Nreal) C[(size_t)r0 * Nreal + c + 8] = v20;
                if (c + 9 < Nreal) C[(size_t)r0 * Nreal + c + 9] = v21;
                if (c + 8 < Nreal) C[(size_t)(r0 + 8) * Nreal + c + 8] = v30;
                if (c + 9 < Nreal) C[(size_t)(r0 + 8) * Nreal + c + 9] = v31;
            }
        }
    }
}

// ---------------------------------------------------------------------------
// Launch
// ---------------------------------------------------------------------------
extern "C" void kernel_launch(void* const* d_in, const int* in_sizes, int n_in,
                              void* d_out, int out_size) {
    const float* x       = (const float*)d_in[0];
    const float* centers = (const float*)d_in[1];
    const float* scales  = (const float*)d_in[2];
    const float* Wb      = (const float*)d_in[3];
    const float* bb      = (const float*)d_in[4];
    const float* Wh      = (const float*)d_in[5];
    const float* bh      = (const float*)d_in[6];
    float* out = (float*)d_out;

    uint4 *F, *PHI, *WbP, *WhP;
    cudaGetSymbolAddress((void**)&F, g_F);
    cudaGetSymbolAddress((void**)&PHI, g_PHI);
    cudaGetSymbolAddress((void**)&WbP, g_WbP);
    cudaGetSymbolAddress((void**)&WhP, g_WhP);

    cudaFuncSetAttribute((const void*)gemm_fp16_kernel<true, true>,
                         cudaFuncAttributeMaxDynamicSharedMemorySize, SMEM_BYTES);
    cudaFuncSetAttribute((const void*)gemm_fp16_kernel<false, false>,
                         cudaFuncAttributeMaxDynamicSharedMemorySize, SMEM_BYTES);

    // 1) feats -> packed fp16 F
    {
        size_t chunks = (size_t)BATCH * KDIM / 8;
        feats_packed_kernel<<<(int)(chunks / 256), 256>>>(x, centers, scales, F);
    }
    // 2) pack Wb, Wh
    {
        size_t cb = (size_t)KDIM * HIDDEN / 8;
        convert_pack_b_kernel<<<(int)(cb / 256), 256>>>(Wb, WbP, KT1, HIDDEN);
        size_t ch = (size_t)HIDDEN * NPAD / 8;
        convert_pack_b_kernel<<<(int)(ch / 256), 256>>>(Wh, WhP, KT2, CLASSES);
    }
    // 3) GEMM1: PHI(packed) = sigmoid(F @ Wb + bb)
    {
        int nT = HIDDEN / 256;                      // 16
        int grid = (BATCH / 128) * nT;              // 512
        gemm_fp16_kernel<true, true><<<grid, 256, SMEM_BYTES>>>(
            F, WbP, bb, PHI, KT1, KT2, HIDDEN, nT);
    }
    // 4) GEMM2: out = PHI @ Wh + bh
    {
        int nT = NPAD / 256;                        // 4
        int grid = (BATCH / 128) * nT;              // 128
        gemm_fp16_kernel<false, false><<<grid, 256, SMEM_BYTES>>>(
            PHI, WhP, bh, out, KT2, 0, CLASSES, nT);
    }
}

// round 6
// speedup vs baseline: 2.2345x; 1.0343x over previous
#include <cuda_runtime.h>
#include <cuda_fp16.h>
#include <cstdint>

// ---------------------------------------------------------------------------
// KANClassifier fp16 mma.sync. Round 6: register double-buffered fragments
// (hide LDS latency under HMMA), single barrier per k-tile.
// ---------------------------------------------------------------------------

#define BATCH   4096
#define IN_DIM  1024
#define KDIM    16384
#define HIDDEN  4096
#define CLASSES 1000
#define NPAD    1024

#define KT1 (KDIM / 32)
#define KT2 (HIDDEN / 32)

__device__ __align__(1024) uint4 g_F  [(size_t)BATCH * KDIM / 8];
__device__ __align__(1024) uint4 g_PHI[(size_t)BATCH * HIDDEN / 8];
__device__ __align__(1024) uint4 g_WbP[(size_t)KDIM * HIDDEN / 8];
__device__ __align__(1024) uint4 g_WhP[(size_t)HIDDEN * NPAD / 8];

__device__ __forceinline__ uint32_t pack_half2(float a, float b) {
    __half2 h = __floats2half2_rn(a, b);
    return *reinterpret_cast<uint32_t*>(&h);
}
__device__ __forceinline__ float mufu_tanh(float v) {
    float r;
    asm("tanh.approx.f32 %0, %1;" : "=f"(r) : "f"(v));
    return r;
}
__device__ __forceinline__ void cp_async16(uint32_t saddr, const void* gptr) {
    asm volatile("cp.async.cg.shared.global [%0], [%1], 16;\n" :: "r"(saddr), "l"(gptr));
}

// ---------------------------------------------------------------------------
// Kernel 1: tanh basis -> g_F packed fp16 (A fragment layout)
// ---------------------------------------------------------------------------
__global__ void feats_packed_kernel(const float* __restrict__ x,
                                    const float* __restrict__ centers,
                                    const float* __restrict__ scales,
                                    uint4* __restrict__ F) {
    int g = blockIdx.x * blockDim.x + threadIdx.x;
    int lane = g & 31, grp = (g >> 5) & 7, ks = (g >> 8) & 1;
    int kt = (g >> 9) & (KT1 - 1), mt = g >> 18;
    int rlo = lane >> 2, klane = lane & 3;
    int r = mt * 128 + grp * 16 + rlo;
    int d = kt * 2 + ks;
    int j0 = klane * 2;

    float xv0 = __ldg(x + (size_t)r * IN_DIM + d);
    float xv1 = __ldg(x + (size_t)(r + 8) * IN_DIM + d);
    const float* cd = centers + d * 16;
    const float* sd = scales + d * 16;
    float c0 = __ldg(cd + j0), c1 = __ldg(cd + j0 + 1);
    float c8 = __ldg(cd + j0 + 8), c9 = __ldg(cd + j0 + 9);
    float s0 = __ldg(sd + j0), s1 = __ldg(sd + j0 + 1);
    float s8 = __ldg(sd + j0 + 8), s9 = __ldg(sd + j0 + 9);

    uint4 o;
    o.x = pack_half2(mufu_tanh((xv0 - c0) * s0), mufu_tanh((xv0 - c1) * s1));
    o.y = pack_half2(mufu_tanh((xv1 - c0) * s0), mufu_tanh((xv1 - c1) * s1));
    o.z = pack_half2(mufu_tanh((xv0 - c8) * s8), mufu_tanh((xv0 - c9) * s9));
    o.w = pack_half2(mufu_tanh((xv1 - c8) * s8), mufu_tanh((xv1 - c9) * s9));
    F[g] = o;
}

// Kernel 2: fp32 W [K][Nsrc] -> packed fp16 B-layout (pad cols >= Nsrc)
__global__ void convert_pack_b_kernel(const float* __restrict__ W,
                                      uint4* __restrict__ out,
                                      int KT, int Nsrc) {
    int g = blockIdx.x * blockDim.x + threadIdx.x;
    int lane = g & 31, npair = (g >> 5) & 15, ks = (g >> 9) & 1;
    int tile = g >> 10;
    int kt = tile % KT, nt = tile / KT;
    int k0 = kt * 32 + ks * 16 + (lane & 3) * 2;
    int c  = nt * 256 + npair * 16 + (lane >> 2);
    int c8 = c + 8;

    const float* w0 = W + (size_t)k0 * Nsrc;
    float a00 = 0.f, a10 = 0.f, a80 = 0.f, a90 = 0.f;
    float a08 = 0.f, a18 = 0.f, a88 = 0.f, a98 = 0.f;
    if (c < Nsrc) {
        a00 = __ldg(w0 + c);
        a10 = __ldg(w0 + Nsrc + c);
        a80 = __ldg(w0 + (size_t)8 * Nsrc + c);
        a90 = __ldg(w0 + (size_t)9 * Nsrc + c);
    }
    if (c8 < Nsrc) {
        a08 = __ldg(w0 + c8);
        a18 = __ldg(w0 + Nsrc + c8);
        a88 = __ldg(w0 + (size_t)8 * Nsrc + c8);
        a98 = __ldg(w0 + (size_t)9 * Nsrc + c8);
    }
    uint4 o;
    o.x = pack_half2(a00, a10);
    o.y = pack_half2(a80, a90);
    o.z = pack_half2(a08, a18);
    o.w = pack_half2(a88, a98);
    out[g] = o;
}

// ---------------------------------------------------------------------------
// fp16 GEMM: 128x256 block, BK=64, 4 stages (192KB), 8 warps (2M x 4N).
// Register double-buffered fragments; one barrier per tile.
// ---------------------------------------------------------------------------
#define STAGES 4
#define A_CH 1024
#define B_CH 2048
#define SMEM_BYTES (STAGES * (A_CH + B_CH) * 16)   // 192KB

__device__ __forceinline__ void mma16816(float* d, const uint4& a,
                                         uint32_t b0, uint32_t b1) {
    asm volatile(
        "mma.sync.aligned.m16n8k16.row.col.f32.f16.f16.f32 "
        "{%0,%1,%2,%3}, {%4,%5,%6,%7}, {%8,%9}, {%0,%1,%2,%3};\n"
        : "+f"(d[0]), "+f"(d[1]), "+f"(d[2]), "+f"(d[3])
        : "r"(a.x), "r"(a.y), "r"(a.z), "r"(a.w), "r"(b0), "r"(b1));
}

template <bool SIGMOID, bool PACKED_OUT>
__global__ void __launch_bounds__(256, 1)
gemm_fp16_kernel(const uint4* __restrict__ Apk,
                 const uint4* __restrict__ Bpk,
                 const float* __restrict__ bias,
                 void* __restrict__ outp,
                 int KTs, int KTout, int Nreal, int nTiles) {
    extern __shared__ uint4 sm4[];
    uint4* As = sm4;
    uint4* Bs = sm4 + STAGES * A_CH;

    const int tid = threadIdx.x;
    const int lane = tid & 31;
    const int warp = tid >> 5;
    const int wm = warp & 1, wn = warp >> 1;
    const int lr = lane >> 2, lc = lane & 3;

    const int GRP = 8;
    int per = GRP * nTiles;
    int mt = (blockIdx.x / per) * GRP + (blockIdx.x % per) % GRP;
    int nt = (blockIdx.x % per) / GRP;
    const int m0 = mt * 128, n0 = nt * 256;
    const int KT2c = KTs / 2;

    float acc[4][8][4];
#pragma unroll
    for (int i = 0; i < 4; i++)
#pragma unroll
        for (int j = 0; j < 8; j++)
#pragma unroll
            for (int k = 0; k < 4; k++) acc[i][j][k] = 0.f;

    auto load_stage = [&](int kt2, int s) {
        const uint4* ag = Apk + ((size_t)mt * KTs + kt2 * 2) * 512;
        uint4* as = As + s * A_CH;
#pragma unroll
        for (int p = 0; p < 4; p++) {
            int ci = tid + p * 256;
            cp_async16((uint32_t)__cvta_generic_to_shared(as + ci), ag + ci);
        }
        const uint4* bg = Bpk + ((size_t)nt * KTs + kt2 * 2) * 1024;
        uint4* bs = Bs + s * B_CH;
#pragma unroll
        for (int p = 0; p < 8; p++) {
            int ci = tid + p * 256;
            cp_async16((uint32_t)__cvta_generic_to_shared(bs + ci), bg + ci);
        }
        asm volatile("cp.async.commit_group;\n");
    };

    load_stage(0, 0);
    load_stage(1, 1);
    load_stage(2, 2);

    for (int kt2 = 0; kt2 < KT2c; kt2++) {
        asm volatile("cp.async.wait_group 2;\n");
        __syncthreads();
        if (kt2 + 3 < KT2c) load_stage(kt2 + 3, (kt2 + 3) & (STAGES - 1));
        else asm volatile("cp.async.commit_group;\n");

        const int s = kt2 & (STAGES - 1);
        const uint4* as = As + s * A_CH;
        const uint4* bs = Bs + s * B_CH;

        uint4 av[2][4], bv[2][4];
#pragma unroll
        for (int mf = 0; mf < 4; mf++)
            av[0][mf] = as[(wm * 4 + mf) * 32 + lane];
#pragma unroll
        for (int np = 0; np < 4; np++)
            bv[0][np] = bs[(wn * 4 + np) * 32 + lane];

#pragma unroll
        for (int ksg = 0; ksg < 4; ksg++) {
            const int cur = ksg & 1, nxt = cur ^ 1;
            if (ksg < 3) {
                const int h2 = (ksg + 1) >> 1, k2 = (ksg + 1) & 1;
#pragma unroll
                for (int mf = 0; mf < 4; mf++)
                    av[nxt][mf] = as[h2 * 512 + k2 * 256 + (wm * 4 + mf) * 32 + lane];
#pragma unroll
                for (int np = 0; np < 4; np++)
                    bv[nxt][np] = bs[h2 * 1024 + (k2 * 16 + wn * 4 + np) * 32 + lane];
            }
#pragma unroll
            for (int mf = 0; mf < 4; mf++)
#pragma unroll
                for (int np = 0; np < 4; np++) {
                    mma16816(acc[mf][2 * np],     av[cur][mf], bv[cur][np].x, bv[cur][np].y);
                    mma16816(acc[mf][2 * np + 1], av[cur][mf], bv[cur][np].z, bv[cur][np].w);
                }
        }
        // no trailing barrier: next iteration's top barrier orders stage reuse
    }

    // ------------------ epilogue ------------------
#pragma unroll
    for (int mf = 0; mf < 4; mf++) {
        const int r0 = m0 + wm * 64 + mf * 16 + lr;
        const int grp = wm * 4 + mf;
#pragma unroll
        for (int npi = 0; npi < 4; npi++) {
            const int nf = npi * 2;
            const int c = n0 + wn * 64 + nf * 8 + lc * 2;
            float b0 = 0.f, b1 = 0.f, b2 = 0.f, b3 = 0.f;
            if (!PACKED_OUT) {
                if (c < Nreal)     b0 = __ldg(bias + c);
                if (c + 1 < Nreal) b1 = __ldg(bias + c + 1);
                if (c + 8 < Nreal) b2 = __ldg(bias + c + 8);
                if (c + 9 < Nreal) b3 = __ldg(bias + c + 9);
            } else {
                b0 = __ldg(bias + c);     b1 = __ldg(bias + c + 1);
                b2 = __ldg(bias + c + 8); b3 = __ldg(bias + c + 9);
            }
            float v00 = acc[mf][nf][0] + b0,     v01 = acc[mf][nf][1] + b1;
            float v10 = acc[mf][nf][2] + b0,     v11 = acc[mf][nf][3] + b1;
            float v20 = acc[mf][nf + 1][0] + b2, v21 = acc[mf][nf + 1][1] + b3;
            float v30 = acc[mf][nf + 1][2] + b2, v31 = acc[mf][nf + 1][3] + b3;
            if (SIGMOID) {
                v00 = 1.f / (1.f + __expf(-v00)); v01 = 1.f / (1.f + __expf(-v01));
                v10 = 1.f / (1.f + __expf(-v10)); v11 = 1.f / (1.f + __expf(-v11));
                v20 = 1.f / (1.f + __expf(-v20)); v21 = 1.f / (1.f + __expf(-v21));
                v30 = 1.f / (1.f + __expf(-v30)); v31 = 1.f / (1.f + __expf(-v31));
            }
            if (PACKED_OUT) {
                int kt2o = c >> 5;
                int ks2 = npi & 1;
                size_t chunk = ((size_t)mt * KTout + kt2o) * 512
                             + ks2 * 256 + grp * 32 + lane;
                uint4 o;
                o.x = pack_half2(v00, v01);
                o.y = pack_half2(v10, v11);
                o.z = pack_half2(v20, v21);
                o.w = pack_half2(v30, v31);
                reinterpret_cast<uint4*>(outp)[chunk] = o;
            } else {
                float* C = reinterpret_cast<float*>(outp);
                if (c < Nreal)     C[(size_t)r0 * Nreal + c] = v00;
                if (c + 1 < Nreal) C[(size_t)r0 * Nreal + c + 1] = v01;
                if (c < Nreal)     C[(size_t)(r0 + 8) * Nreal + c] = v10;
                if (c + 1 < Nreal) C[(size_t)(r0 + 8) * Nreal + c + 1] = v11;
                if (c + 8 < Nreal) C[(size_t)r0 * Nreal + c + 8] = v20;
                if (c + 9 < Nreal) C[(size_t)r0 * Nreal + c + 9] = v21;
                if (c + 8 < Nreal) C[(size_t)(r0 + 8) * Nreal + c + 8] = v30;
                if (c + 9 < Nreal) C[(size_t)(r0 + 8) * Nreal + c + 9] = v31;
            }
        }
    }
}

// ---------------------------------------------------------------------------
// Launch
// ---------------------------------------------------------------------------
extern "C" void kernel_launch(void* const* d_in, const int* in_sizes, int n_in,
                              void* d_out, int out_size) {
    const float* x       = (const float*)d_in[0];
    const float* centers = (const float*)d_in[1];
    const float* scales  = (const float*)d_in[2];
    const float* Wb      = (const float*)d_in[3];
    const float* bb      = (const float*)d_in[4];
    const float* Wh      = (const float*)d_in[5];
    const float* bh      = (const float*)d_in[6];
    float* out = (float*)d_out;

    uint4 *F, *PHI, *WbP, *WhP;
    cudaGetSymbolAddress((void**)&F, g_F);
    cudaGetSymbolAddress((void**)&PHI, g_PHI);
    cudaGetSymbolAddress((void**)&WbP, g_WbP);
    cudaGetSymbolAddress((void**)&WhP, g_WhP);

    cudaFuncSetAttribute((const void*)gemm_fp16_kernel<true, true>,
                         cudaFuncAttributeMaxDynamicSharedMemorySize, SMEM_BYTES);
    cudaFuncSetAttribute((const void*)gemm_fp16_kernel<false, false>,
                         cudaFuncAttributeMaxDynamicSharedMemorySize, SMEM_BYTES);

    // 1) feats -> packed fp16 F
    {
        size_t chunks = (size_t)BATCH * KDIM / 8;
        feats_packed_kernel<<<(int)(chunks / 256), 256>>>(x, centers, scales, F);
    }
    // 2) pack Wb, Wh
    {
        size_t cb = (size_t)KDIM * HIDDEN / 8;
        convert_pack_b_kernel<<<(int)(cb / 256), 256>>>(Wb, WbP, KT1, HIDDEN);
        size_t ch = (size_t)HIDDEN * NPAD / 8;
        convert_pack_b_kernel<<<(int)(ch / 256), 256>>>(Wh, WhP, KT2, CLASSES);
    }
    // 3) GEMM1: PHI(packed) = sigmoid(F @ Wb + bb)
    {
        int nT = HIDDEN / 256;
        int grid = (BATCH / 128) * nT;
        gemm_fp16_kernel<true, true><<<grid, 256, SMEM_BYTES>>>(
            F, WbP, bb, PHI, KT1, KT2, HIDDEN, nT);
    }
    // 4) GEMM2: out = PHI @ Wh + bh
    {
        int nT = NPAD / 256;
        int grid = (BATCH / 128) * nT;
        gemm_fp16_kernel<false, false><<<grid, 256, SMEM_BYTES>>>(
            PHI, WhP, bh, out, KT2, 0, CLASSES, nT);
    }
}